// round 15
// baseline (speedup 1.0000x reference)
#include <cuda_runtime.h>
#include <math.h>

// Shapes (hardcoded from reference): B=16, N=32, C=8, O=16
// d_in order: x0, x1, x2, x3, W0, b0, W1, b1, W2, b2, W3, b3
// d_out: concat(out0[16,16], out1[16,32,16], out2[16,32,32,16], out3[16,32,32,32,16])

__device__ __forceinline__ float sigm(float x) {
    return __fdividef(1.0f, 1.0f + __expf(-x));
}

// Packed fp32x2 helpers (sm_100+). Per-lane rounding identical to scalar FFMA.
#define FFMA2(ACC, S, W) \
    asm("fma.rn.f32x2 %0, %1, %2, %0;" : "+l"(ACC) : "l"(S), "l"(W))
#define ADD2(D, A, B) \
    asm("add.rn.f32x2 %0, %1, %2;" : "=l"(D) : "l"(A), "l"(B))
#define PACK2(D, F) \
    asm("mov.b64 %0, {%1, %1};" : "=l"(D) : "r"(__float_as_uint(F)))
#define UNPACK2(LO, HI, A) \
    asm("mov.b64 {%0, %1}, %2;" : "=r"(LO), "=r"(HI) : "l"(A))

// ---------------------------------------------------------------------------
// ONE fused kernel. grid = 530 CTAs x 1024 threads, 231.9KB dyn smem.
//   blk <  512 : main, (b,i) = (blk>>5, blk&31) -> out3
//   512..527   : out2 for b = blk-512 (self-computes reduce(x3) rows)
//   528        : out1 (all b)
//   529        : out0
//
// Main smem: 3 x3-slices (PITCH 388, stride-12 slots: disjoint, 16B-aligned,
// conflict-free both row- and column-indexed — verified in R12), hot weights,
// sA/sC, and a per-CTA T45 table (stride-18 rows, bank-clean LDS.64):
//   T45[j,k][o] = b3 + sA[j] + sC[k] + x2[b,j,k]·W3[64:72] + x2[b,k,j]·W3[80:88]
// Hot loop (6 x3 terms only — fastest measured structure):
//   acc = T45(LDS) + sum_t v_t . W_t ; sigmoid ; store.
//
// R15 fix vs R14: SM_W45 (512 floats = W3 rows 64..95) is staged by its own
// tid<512 predicate. R14's "else if (tid < 768+512)" only covered 256 entries
// (tid 768..1023), leaving rows 80..95 uninitialized -> out3 rel_err 3.9e-2.
// ---------------------------------------------------------------------------
#define PITCH 388
#define SLICE (32 * PITCH)               // 12416 floats
#define SM_S1 0
#define SM_S2 SLICE
#define SM_S3 (2 * SLICE)
#define SM_W   (3 * SLICE)               // 768: hot weights [t][cc][16]
#define SM_A   (3 * SLICE + 768)         // 512
#define SM_C   (3 * SLICE + 1280)        // 512
#define SM_T45 (3 * SLICE + 1792)        // 1024 rows x 18 = 18432
#define SM_W45 (3 * SLICE + 20224)       // 512: W3 rows 64..95 as [r-64][16]
#define SM_FLOATS (3 * SLICE + 20736)    // 57984 floats = 231936 bytes

__global__ void __launch_bounds__(1024) k_fused(
    const float* __restrict__ x0, const float* __restrict__ x1,
    const float* __restrict__ x2, const float* __restrict__ x3,
    const float* __restrict__ W0, const float* __restrict__ b0,
    const float* __restrict__ W1, const float* __restrict__ b1,
    const float* __restrict__ W2, const float* __restrict__ b2,
    const float* __restrict__ W3, const float* __restrict__ b3,
    float* __restrict__ out0, float* __restrict__ out1,
    float* __restrict__ out2, float* __restrict__ out3)
{
    extern __shared__ __align__(16) float sm[];
    int blk = blockIdx.x;
    int tid = threadIdx.x;

    if (blk < 512) {
        // =================== MAIN: out3 for (b,i) ===================
        int b = blk >> 5;
        int i = blk & 31;
        const float* x3b = x3 + (size_t)b * 32 * 32 * 32 * 8;
        const float* x2b = x2 + (size_t)b * 8192;

        // ---- Phase A: stage slices + weights ----
        {
            const float4* src = (const float4*)(x3b + i * 8192);
            for (int idx = tid; idx < 2048; idx += 1024) {
                int r = idx >> 6, w = idx & 63;
                int kk = w >> 1, hf = w & 1;
                *(float4*)(sm + SM_S1 + r * PITCH + kk * 12 + hf * 4) = src[idx];
            }
        }
        for (int idx = tid; idx < 2048; idx += 1024) {
            int a = idx >> 6, w = idx & 63;
            int kk = w >> 1, hf = w & 1;
            float4 v = *(const float4*)(x3b + a * 8192 + i * 256 + w * 4);
            *(float4*)(sm + SM_S2 + a * PITCH + kk * 12 + hf * 4) = v;
        }
        for (int idx = tid; idx < 2048; idx += 1024) {
            int ch = idx >> 1, hf = idx & 1;
            int a1 = ch >> 5, a2 = ch & 31;
            float4 v = *(const float4*)(x3b + a1 * 8192 + a2 * 256 + i * 8 + hf * 4);
            *(float4*)(sm + SM_S3 + a1 * PITCH + a2 * 12 + hf * 4) = v;
        }
        if (tid < 768) {             // hot weights: rows 16t+8+cc
            int term = tid >> 7;
            int r = tid & 127;
            int cc = r >> 4, o = r & 15;
            sm[SM_W + tid] = W3[(16 * term + 8 + cc) * 16 + o];
        }
        if (tid < 512) {             // W45: W3 rows 64..95 (ALL 512 floats)
            sm[SM_W45 + tid] = W3[1024 + tid];
        }
        // sA[j][o] (p0/p2 x2-terms), sC[k][o] (p1/p3) — global reads, one-time
        if (tid < 512) {
            int j = tid >> 4, o = tid & 15;
            float accA = 0.0f, accC = 0.0f;
            #pragma unroll
            for (int cc = 0; cc < 8; cc++) {
                float xij = x2b[(i * 32 + j) * 8 + cc];
                float xji = x2b[(j * 32 + i) * 8 + cc];
                accA += xij * W3[cc * 16 + o] + xji * W3[(32 + cc) * 16 + o];
                accC += xij * W3[(16 + cc) * 16 + o] + xji * W3[(48 + cc) * 16 + o];
            }
            sm[SM_A + tid] = accA;
            sm[SM_C + tid] = accC;
        }
        __syncthreads();

        // ---- Phase B: build T45[jk] = b3 + sA[j] + sC[k] + x2-pair terms ----
        {
            int j = tid >> 5, k = tid & 31;
            unsigned long long t45[8];
            const unsigned long long* pb = (const unsigned long long*)b3;
            const unsigned long long* pa = (const unsigned long long*)(sm + SM_A + j * 16);
            const unsigned long long* pc = (const unsigned long long*)(sm + SM_C + k * 16);
            #pragma unroll
            for (int q = 0; q < 8; q++) {
                unsigned long long t;
                ADD2(t, pa[q], pc[q]);
                ADD2(t, t, pb[q]);
                t45[q] = t;
            }
            const float* xjk = x2b + (j * 32 + k) * 8;
            const float* xkj = x2b + (k * 32 + j) * 8;
            #pragma unroll
            for (int cc = 0; cc < 8; cc++) {
                unsigned long long p4, p5;
                PACK2(p4, xjk[cc]);
                PACK2(p5, xkj[cc]);
                const unsigned long long* w4 = (const unsigned long long*)(sm + SM_W45 + cc * 16);
                const unsigned long long* w5 = (const unsigned long long*)(sm + SM_W45 + (16 + cc) * 16);
                #pragma unroll
                for (int q = 0; q < 8; q++) {
                    FFMA2(t45[q], p4, w4[q]);
                    FFMA2(t45[q], p5, w5[q]);
                }
            }
            unsigned long long* dst = (unsigned long long*)(sm + SM_T45 + tid * 18);
            #pragma unroll
            for (int q = 0; q < 8; q++) dst[q] = t45[q];
        }
        __syncthreads();

        // ---- Phase C: hot loop (R12-verified), 2 pos x 8 ch per thread ----
        int half = tid >> 9;
        int o0 = half * 8;
        int idx = tid & 511;
        int k = idx & 31;
        int jp = idx >> 5;            // j = jp*2 + g

        unsigned long long acc[2][4];
        #pragma unroll
        for (int g = 0; g < 2; g++) {
            int j = jp * 2 + g;
            const unsigned long long* t45 =
                (const unsigned long long*)(sm + SM_T45 + (j * 32 + k) * 18 + o0);
            #pragma unroll
            for (int q = 0; q < 4; q++) acc[g][q] = t45[q];
        }

        int rowbase = (jp * 2) * PITCH + k * 12;        // + g*PITCH per pos
        int colword0 = k * PITCH + (jp * 2) * 12;
        int colword1 = colword0 + 12;

        #pragma unroll
        for (int t = 0; t < 6; t++) {
            const float* sl = sm + (t >> 1) * SLICE;
            float v[2][8];
            #pragma unroll
            for (int g = 0; g < 2; g++) {
                const float* p = (t & 1)
                    ? (sl + (g ? colword1 : colword0))
                    : (sl + rowbase + g * PITCH);
                float4 lo = *(const float4*)p;
                float4 hi = *(const float4*)(p + 4);
                v[g][0] = lo.x; v[g][1] = lo.y; v[g][2] = lo.z; v[g][3] = lo.w;
                v[g][4] = hi.x; v[g][5] = hi.y; v[g][6] = hi.z; v[g][7] = hi.w;
            }
            const float* wt = sm + SM_W + t * 128 + o0;
            #pragma unroll
            for (int cc = 0; cc < 8; cc++) {
                const unsigned long long* w4 = (const unsigned long long*)(wt + cc * 16);
                unsigned long long w0 = w4[0], w1 = w4[1], w2 = w4[2], w3 = w4[3];
                #pragma unroll
                for (int g = 0; g < 2; g++) {
                    unsigned long long s2p;
                    PACK2(s2p, v[g][cc]);
                    FFMA2(acc[g][0], s2p, w0);
                    FFMA2(acc[g][1], s2p, w1);
                    FFMA2(acc[g][2], s2p, w2);
                    FFMA2(acc[g][3], s2p, w3);
                }
            }
        }

        #pragma unroll
        for (int g = 0; g < 2; g++) {
            int j = jp * 2 + g;
            float r[8];
            #pragma unroll
            for (int q = 0; q < 4; q++) {
                unsigned int lo, hi;
                UNPACK2(lo, hi, acc[g][q]);
                r[q * 2 + 0] = sigm(__uint_as_float(lo));
                r[q * 2 + 1] = sigm(__uint_as_float(hi));
            }
            float* dst = out3 + ((((size_t)b * 32 + i) * 32 + j) * 32 + k) * 16 + o0;
            *(float4*)dst = make_float4(r[0], r[1], r[2], r[3]);
            *(float4*)(dst + 4) = make_float4(r[4], r[5], r[6], r[7]);
        }

    } else if (blk < 528) {
        // =================== out2 for batch b (self-computed R3) ===========
        int b = blk - 512;
        const float* x3b = x3 + (size_t)b * 32 * 32 * 32 * 8;
        float* sR3 = sm;                 // [1024 pos][16]
        float* sW2 = sm + 16384;         // [64][16]

        // Phase 1: sR3[pos=(i,j)][max8|min8] = masked reduce over a3 (a3==j)
        #pragma unroll
        for (int s = 0; s < 8; s++) {
            int task = s * 1024 + tid;   // (pos, c)
            int pos = task >> 3, c = task & 7;
            int j = pos & 31;
            const float* p = x3b + pos * 256 + c;
            float vmax = -INFINITY, vmin = INFINITY;
            #pragma unroll 8
            for (int a = 0; a < 32; a++) {
                float v = p[a * 8];
                float vm = (a == j) ? 0.0f : v;
                float vn = (a == j) ? 1.0f : v;
                vmax = fmaxf(vmax, vm);
                vmin = fminf(vmin, vn);
            }
            sR3[pos * 16 + c] = vmax;
            sR3[pos * 16 + 8 + c] = vmin;
        }
        if (tid < 1024) sW2[tid] = W2[tid];
        __syncthreads();

        // Phase 2: 2 half-tasks per thread
        #pragma unroll
        for (int s = 0; s < 2; s++) {
            int tt = s * 1024 + tid;
            int half = tt & 1;
            int p2 = tt >> 1;            // (i,j)
            int j = p2 & 31, i = p2 >> 5;
            int o0 = half * 8;

            float acc[8];
            #pragma unroll
            for (int o = 0; o < 8; o++) acc[o] = b2[o0 + o];

            #define ACC_SRC(PTR, RB_, CNT)                                     \
                {                                                              \
                    const float* _s = (PTR);                                   \
                    _Pragma("unroll")                                          \
                    for (int c = 0; c < (CNT); c++) {                          \
                        float v = _s[c];                                       \
                        const float* w = sW2 + ((RB_) + c) * 16 + o0;          \
                        _Pragma("unroll")                                      \
                        for (int o = 0; o < 8; o++) acc[o] += v * w[o];        \
                    }                                                          \
                }
            ACC_SRC(x1 + (b * 32 + i) * 8, 0, 8);
            ACC_SRC(x2 + ((b * 32 + i) * 32 + j) * 8, 8, 8);
            ACC_SRC(sR3 + (i * 32 + j) * 16, 16, 16);
            ACC_SRC(x1 + (b * 32 + j) * 8, 32, 8);
            ACC_SRC(x2 + ((b * 32 + j) * 32 + i) * 8, 40, 8);
            ACC_SRC(sR3 + (j * 32 + i) * 16, 48, 16);
            #undef ACC_SRC

            float* dst = out2 + ((size_t)b * 1024 + p2) * 16 + o0;
            #pragma unroll
            for (int o = 0; o < 8; o++) dst[o] = sigm(acc[o]);
        }

    } else if (blk == 528) {
        // =================== out1 (all batches) ===================
        float* sMax = sm;                // [16*32*8]
        float* sMin = sm + 4096;
        float* sW1 = sm + 8192;          // [32][16]

        #pragma unroll
        for (int s = 0; s < 4; s++) {
            int task = s * 1024 + tid;   // (b,i,c)
            int b = task >> 8, i = (task >> 3) & 31, c = task & 7;
            const float* p = x2 + ((b * 32 + i) * 32) * 8 + c;
            float vmax = -INFINITY, vmin = INFINITY;
            #pragma unroll 8
            for (int a = 0; a < 32; a++) {
                float v = p[a * 8];
                float vm = (a == i) ? 0.0f : v;
                float vn = (a == i) ? 1.0f : v;
                vmax = fmaxf(vmax, vm);
                vmin = fminf(vmin, vn);
            }
            sMax[task] = vmax;
            sMin[task] = vmin;
        }
        if (tid < 512) sW1[tid] = W1[tid];
        __syncthreads();

        #pragma unroll
        for (int s = 0; s < 8; s++) {
            int tt = s * 1024 + tid;     // (b,i,o)
            int b = tt >> 9, i = (tt >> 4) & 31, o = tt & 15;
            float acc = b1[o];
            const float* x1i = x1 + (b * 32 + i) * 8;
            const float* x0b = x0 + b * 8;
            int rbase = b * 256 + i * 8;
            #pragma unroll
            for (int c = 0; c < 8; c++) {
                acc += x0b[c] * sW1[c * 16 + o];
                acc += x1i[c] * sW1[(8 + c) * 16 + o];
                acc += sMax[rbase + c] * sW1[(16 + c) * 16 + o];
                acc += sMin[rbase + c] * sW1[(24 + c) * 16 + o];
            }
            out1[(size_t)(b * 32 + i) * 16 + o] = sigm(acc);
        }

    } else {
        // =================== out0 ===================
        float* sMax0 = sm;               // [16*8]
        float* sMin0 = sm + 128;
        if (tid < 128) {
            int b = tid >> 3, c = tid & 7;
            const float* p = x1 + (b * 32) * 8 + c;
            float vmax = -INFINITY, vmin = INFINITY;
            #pragma unroll 8
            for (int n = 0; n < 32; n++) {
                float v = p[n * 8];
                vmax = fmaxf(vmax, v);
                vmin = fminf(vmin, v);
            }
            sMax0[tid] = vmax;
            sMin0[tid] = vmin;
        }
        __syncthreads();
        if (tid < 256) {
            int b = tid >> 4, o = tid & 15;
            float acc = b0[o];
            const float* x0b = x0 + b * 8;
            #pragma unroll
            for (int c = 0; c < 8; c++) {
                acc += x0b[c] * W0[c * 16 + o];
                acc += sMax0[b * 8 + c] * W0[(8 + c) * 16 + o];
                acc += sMin0[b * 8 + c] * W0[(16 + c) * 16 + o];
            }
            out0[b * 16 + o] = sigm(acc);
        }
    }
}

// ---------------------------------------------------------------------------
extern "C" void kernel_launch(void* const* d_in, const int* in_sizes, int n_in,
                              void* d_out, int out_size)
{
    const float* x0 = (const float*)d_in[0];
    const float* x1 = (const float*)d_in[1];
    const float* x2 = (const float*)d_in[2];
    const float* x3 = (const float*)d_in[3];
    const float* W0 = (const float*)d_in[4];
    const float* b0 = (const float*)d_in[5];
    const float* W1 = (const float*)d_in[6];
    const float* b1 = (const float*)d_in[7];
    const float* W2 = (const float*)d_in[8];
    const float* b2 = (const float*)d_in[9];
    const float* W3 = (const float*)d_in[10];
    const float* b3 = (const float*)d_in[11];

    float* out = (float*)d_out;
    float* out0 = out;                 // [16,16]            =     256
    float* out1 = out + 256;           // [16,32,16]         =    8192
    float* out2 = out + 8448;          // [16,32,32,16]      =  262144
    float* out3 = out + 270592;        // [16,32,32,32,16]   = 8388608

    const int smem_bytes = SM_FLOATS * 4;  // 231936
    cudaFuncSetAttribute(k_fused, cudaFuncAttributeMaxDynamicSharedMemorySize, smem_bytes);

    k_fused<<<530, 1024, smem_bytes>>>(x0, x1, x2, x3, W0, b0, W1, b1,
                                       W2, b2, W3, b3, out0, out1, out2, out3);
}

// round 16
// speedup vs baseline: 1.0176x; 1.0176x over previous
#include <cuda_runtime.h>
#include <math.h>

// Shapes (hardcoded from reference): B=16, N=32, C=8, O=16
// d_in order: x0, x1, x2, x3, W0, b0, W1, b1, W2, b2, W3, b3
// d_out: concat(out0[16,16], out1[16,32,16], out2[16,32,32,16], out3[16,32,32,32,16])

__device__ __forceinline__ float sigm(float x) {
    return __fdividef(1.0f, 1.0f + __expf(-x));
}

// Packed fp32x2 helpers (sm_100+). Per-lane rounding identical to scalar FFMA.
#define FFMA2(ACC, S, W) \
    asm("fma.rn.f32x2 %0, %1, %2, %0;" : "+l"(ACC) : "l"(S), "l"(W))
#define ADD2(D, A, B) \
    asm("add.rn.f32x2 %0, %1, %2;" : "=l"(D) : "l"(A), "l"(B))
#define PACK2(D, F) \
    asm("mov.b64 %0, {%1, %1};" : "=l"(D) : "r"(__float_as_uint(F)))
#define UNPACK2(LO, HI, A) \
    asm("mov.b64 {%0, %1}, %2;" : "=r"(LO), "=r"(HI) : "l"(A))

// ---------------------------------------------------------------------------
// ONE fused kernel. grid = 530 CTAs x 1024 threads, 231.9KB dyn smem.
//   blk <  512 : main, (b,i) = (blk>>5, blk&31) -> out3
//   512..527   : out2 for b = blk-512 (self-computes reduce(x3) rows)
//   528        : out1 (all b)
//   529        : out0
//
// R16 vs R15: Phase B (T45 build) runs as TWO half-channel passes with only
// 4 u64 accumulators live (task = (pos, half)), halving its register peak.
// R15 hit the 64-reg cap (1024 thr) and spilled -> fma% 25.7->12, 2.2x slow.
// Hot loop is the R12/R13-proven 46-reg shape, untouched.
// ---------------------------------------------------------------------------
#define PITCH 388
#define SLICE (32 * PITCH)               // 12416 floats
#define SM_S1 0
#define SM_S2 SLICE
#define SM_S3 (2 * SLICE)
#define SM_W   (3 * SLICE)               // 768: hot weights [t][cc][16]
#define SM_A   (3 * SLICE + 768)         // 512
#define SM_C   (3 * SLICE + 1280)        // 512
#define SM_T45 (3 * SLICE + 1792)        // 1024 rows x 18 = 18432
#define SM_W45 (3 * SLICE + 20224)       // 512: W3 rows 64..95 as [r-64][16]
#define SM_FLOATS (3 * SLICE + 20736)    // 57984 floats = 231936 bytes

__global__ void __launch_bounds__(1024) k_fused(
    const float* __restrict__ x0, const float* __restrict__ x1,
    const float* __restrict__ x2, const float* __restrict__ x3,
    const float* __restrict__ W0, const float* __restrict__ b0,
    const float* __restrict__ W1, const float* __restrict__ b1,
    const float* __restrict__ W2, const float* __restrict__ b2,
    const float* __restrict__ W3, const float* __restrict__ b3,
    float* __restrict__ out0, float* __restrict__ out1,
    float* __restrict__ out2, float* __restrict__ out3)
{
    extern __shared__ __align__(16) float sm[];
    int blk = blockIdx.x;
    int tid = threadIdx.x;

    if (blk < 512) {
        // =================== MAIN: out3 for (b,i) ===================
        int b = blk >> 5;
        int i = blk & 31;
        const float* x3b = x3 + (size_t)b * 32 * 32 * 32 * 8;
        const float* x2b = x2 + (size_t)b * 8192;

        // ---- Phase A: stage slices + weights ----
        {
            const float4* src = (const float4*)(x3b + i * 8192);
            for (int idx = tid; idx < 2048; idx += 1024) {
                int r = idx >> 6, w = idx & 63;
                int kk = w >> 1, hf = w & 1;
                *(float4*)(sm + SM_S1 + r * PITCH + kk * 12 + hf * 4) = src[idx];
            }
        }
        for (int idx = tid; idx < 2048; idx += 1024) {
            int a = idx >> 6, w = idx & 63;
            int kk = w >> 1, hf = w & 1;
            float4 v = *(const float4*)(x3b + a * 8192 + i * 256 + w * 4);
            *(float4*)(sm + SM_S2 + a * PITCH + kk * 12 + hf * 4) = v;
        }
        for (int idx = tid; idx < 2048; idx += 1024) {
            int ch = idx >> 1, hf = idx & 1;
            int a1 = ch >> 5, a2 = ch & 31;
            float4 v = *(const float4*)(x3b + a1 * 8192 + a2 * 256 + i * 8 + hf * 4);
            *(float4*)(sm + SM_S3 + a1 * PITCH + a2 * 12 + hf * 4) = v;
        }
        if (tid < 768) {             // hot weights: rows 16t+8+cc
            int term = tid >> 7;
            int r = tid & 127;
            int cc = r >> 4, o = r & 15;
            sm[SM_W + tid] = W3[(16 * term + 8 + cc) * 16 + o];
        }
        if (tid < 512) {             // W45: W3 rows 64..95 (all 512 floats)
            sm[SM_W45 + tid] = W3[1024 + tid];
        }
        // sA[j][o] (p0/p2 x2-terms, incl b3), sC[k][o] (p1/p3)
        if (tid < 512) {
            int j = tid >> 4, o = tid & 15;
            float accA = b3[o], accC = 0.0f;
            #pragma unroll
            for (int cc = 0; cc < 8; cc++) {
                float xij = x2b[(i * 32 + j) * 8 + cc];
                float xji = x2b[(j * 32 + i) * 8 + cc];
                accA += xij * W3[cc * 16 + o] + xji * W3[(32 + cc) * 16 + o];
                accC += xij * W3[(16 + cc) * 16 + o] + xji * W3[(48 + cc) * 16 + o];
            }
            sm[SM_A + tid] = accA;
            sm[SM_C + tid] = accC;
        }
        __syncthreads();

        // ---- Phase B: T45[pos][o] = sA[j]+sC[k] + x2-pair terms ----
        // Two half-channel passes: task = (pos, half); 4 u64 accs live only.
        #pragma unroll
        for (int s = 0; s < 2; s++) {
            int task = s * 1024 + tid;      // 2048 tasks
            int hf = task & 1;
            int pos = task >> 1;            // (j,k)
            int j = pos >> 5, k = pos & 31;
            int of = hf * 8;

            unsigned long long t45[4];
            const unsigned long long* pa = (const unsigned long long*)(sm + SM_A + j * 16 + of);
            const unsigned long long* pc = (const unsigned long long*)(sm + SM_C + k * 16 + of);
            #pragma unroll
            for (int q = 0; q < 4; q++) {
                unsigned long long t;
                ADD2(t, pa[q], pc[q]);
                t45[q] = t;
            }
            const float* xjk = x2b + pos * 8;              // x2[b,j,k]
            const float* xkj = x2b + (k * 32 + j) * 8;     // x2[b,k,j]
            #pragma unroll
            for (int cc = 0; cc < 8; cc++) {
                unsigned long long p4, p5;
                PACK2(p4, xjk[cc]);
                PACK2(p5, xkj[cc]);
                const unsigned long long* w4 =
                    (const unsigned long long*)(sm + SM_W45 + cc * 16 + of);
                const unsigned long long* w5 =
                    (const unsigned long long*)(sm + SM_W45 + (16 + cc) * 16 + of);
                #pragma unroll
                for (int q = 0; q < 4; q++) {
                    FFMA2(t45[q], p4, w4[q]);
                    FFMA2(t45[q], p5, w5[q]);
                }
            }
            unsigned long long* dst = (unsigned long long*)(sm + SM_T45 + pos * 18 + of);
            #pragma unroll
            for (int q = 0; q < 4; q++) dst[q] = t45[q];
        }
        __syncthreads();

        // ---- Phase C: hot loop (R12-verified), 2 pos x 8 ch per thread ----
        int half = tid >> 9;
        int o0 = half * 8;
        int idx = tid & 511;
        int k = idx & 31;
        int jp = idx >> 5;            // j = jp*2 + g

        unsigned long long acc[2][4];
        #pragma unroll
        for (int g = 0; g < 2; g++) {
            int j = jp * 2 + g;
            const unsigned long long* t45 =
                (const unsigned long long*)(sm + SM_T45 + (j * 32 + k) * 18 + o0);
            #pragma unroll
            for (int q = 0; q < 4; q++) acc[g][q] = t45[q];
        }

        int rowbase = (jp * 2) * PITCH + k * 12;        // + g*PITCH per pos
        int colword0 = k * PITCH + (jp * 2) * 12;
        int colword1 = colword0 + 12;

        #pragma unroll
        for (int t = 0; t < 6; t++) {
            const float* sl = sm + (t >> 1) * SLICE;
            float v[2][8];
            #pragma unroll
            for (int g = 0; g < 2; g++) {
                const float* p = (t & 1)
                    ? (sl + (g ? colword1 : colword0))
                    : (sl + rowbase + g * PITCH);
                float4 lo = *(const float4*)p;
                float4 hi = *(const float4*)(p + 4);
                v[g][0] = lo.x; v[g][1] = lo.y; v[g][2] = lo.z; v[g][3] = lo.w;
                v[g][4] = hi.x; v[g][5] = hi.y; v[g][6] = hi.z; v[g][7] = hi.w;
            }
            const float* wt = sm + SM_W + t * 128 + o0;
            #pragma unroll
            for (int cc = 0; cc < 8; cc++) {
                const unsigned long long* w4 = (const unsigned long long*)(wt + cc * 16);
                unsigned long long w0 = w4[0], w1 = w4[1], w2 = w4[2], w3 = w4[3];
                #pragma unroll
                for (int g = 0; g < 2; g++) {
                    unsigned long long s2p;
                    PACK2(s2p, v[g][cc]);
                    FFMA2(acc[g][0], s2p, w0);
                    FFMA2(acc[g][1], s2p, w1);
                    FFMA2(acc[g][2], s2p, w2);
                    FFMA2(acc[g][3], s2p, w3);
                }
            }
        }

        #pragma unroll
        for (int g = 0; g < 2; g++) {
            int j = jp * 2 + g;
            float r[8];
            #pragma unroll
            for (int q = 0; q < 4; q++) {
                unsigned int lo, hi;
                UNPACK2(lo, hi, acc[g][q]);
                r[q * 2 + 0] = sigm(__uint_as_float(lo));
                r[q * 2 + 1] = sigm(__uint_as_float(hi));
            }
            float* dst = out3 + ((((size_t)b * 32 + i) * 32 + j) * 32 + k) * 16 + o0;
            *(float4*)dst = make_float4(r[0], r[1], r[2], r[3]);
            *(float4*)(dst + 4) = make_float4(r[4], r[5], r[6], r[7]);
        }

    } else if (blk < 528) {
        // =================== out2 for batch b (self-computed R3) ===========
        int b = blk - 512;
        const float* x3b = x3 + (size_t)b * 32 * 32 * 32 * 8;
        float* sR3 = sm;                 // [1024 pos][16]
        float* sW2 = sm + 16384;         // [64][16]

        // Phase 1: sR3[pos=(i,j)][max8|min8] = masked reduce over a3 (a3==j)
        #pragma unroll
        for (int s = 0; s < 8; s++) {
            int task = s * 1024 + tid;   // (pos, c)
            int pos = task >> 3, c = task & 7;
            int j = pos & 31;
            const float* p = x3b + pos * 256 + c;
            float vmax = -INFINITY, vmin = INFINITY;
            #pragma unroll 8
            for (int a = 0; a < 32; a++) {
                float v = p[a * 8];
                float vm = (a == j) ? 0.0f : v;
                float vn = (a == j) ? 1.0f : v;
                vmax = fmaxf(vmax, vm);
                vmin = fminf(vmin, vn);
            }
            sR3[pos * 16 + c] = vmax;
            sR3[pos * 16 + 8 + c] = vmin;
        }
        if (tid < 1024) sW2[tid] = W2[tid];
        __syncthreads();

        // Phase 2: 2 half-tasks per thread
        #pragma unroll
        for (int s = 0; s < 2; s++) {
            int tt = s * 1024 + tid;
            int half = tt & 1;
            int p2 = tt >> 1;            // (i,j)
            int j = p2 & 31, i = p2 >> 5;
            int o0 = half * 8;

            float acc[8];
            #pragma unroll
            for (int o = 0; o < 8; o++) acc[o] = b2[o0 + o];

            #define ACC_SRC(PTR, RB_, CNT)                                     \
                {                                                              \
                    const float* _s = (PTR);                                   \
                    _Pragma("unroll")                                          \
                    for (int c = 0; c < (CNT); c++) {                          \
                        float v = _s[c];                                       \
                        const float* w = sW2 + ((RB_) + c) * 16 + o0;          \
                        _Pragma("unroll")                                      \
                        for (int o = 0; o < 8; o++) acc[o] += v * w[o];        \
                    }                                                          \
                }
            ACC_SRC(x1 + (b * 32 + i) * 8, 0, 8);
            ACC_SRC(x2 + ((b * 32 + i) * 32 + j) * 8, 8, 8);
            ACC_SRC(sR3 + (i * 32 + j) * 16, 16, 16);
            ACC_SRC(x1 + (b * 32 + j) * 8, 32, 8);
            ACC_SRC(x2 + ((b * 32 + j) * 32 + i) * 8, 40, 8);
            ACC_SRC(sR3 + (j * 32 + i) * 16, 48, 16);
            #undef ACC_SRC

            float* dst = out2 + ((size_t)b * 1024 + p2) * 16 + o0;
            #pragma unroll
            for (int o = 0; o < 8; o++) dst[o] = sigm(acc[o]);
        }

    } else if (blk == 528) {
        // =================== out1 (all batches) ===================
        float* sMax = sm;                // [16*32*8]
        float* sMin = sm + 4096;
        float* sW1 = sm + 8192;          // [32][16]

        #pragma unroll
        for (int s = 0; s < 4; s++) {
            int task = s * 1024 + tid;   // (b,i,c)
            int b = task >> 8, i = (task >> 3) & 31, c = task & 7;
            const float* p = x2 + ((b * 32 + i) * 32) * 8 + c;
            float vmax = -INFINITY, vmin = INFINITY;
            #pragma unroll 8
            for (int a = 0; a < 32; a++) {
                float v = p[a * 8];
                float vm = (a == i) ? 0.0f : v;
                float vn = (a == i) ? 1.0f : v;
                vmax = fmaxf(vmax, vm);
                vmin = fminf(vmin, vn);
            }
            sMax[task] = vmax;
            sMin[task] = vmin;
        }
        if (tid < 512) sW1[tid] = W1[tid];
        __syncthreads();

        #pragma unroll
        for (int s = 0; s < 8; s++) {
            int tt = s * 1024 + tid;     // (b,i,o)
            int b = tt >> 9, i = (tt >> 4) & 31, o = tt & 15;
            float acc = b1[o];
            const float* x1i = x1 + (b * 32 + i) * 8;
            const float* x0b = x0 + b * 8;
            int rbase = b * 256 + i * 8;
            #pragma unroll
            for (int c = 0; c < 8; c++) {
                acc += x0b[c] * sW1[c * 16 + o];
                acc += x1i[c] * sW1[(8 + c) * 16 + o];
                acc += sMax[rbase + c] * sW1[(16 + c) * 16 + o];
                acc += sMin[rbase + c] * sW1[(24 + c) * 16 + o];
            }
            out1[(size_t)(b * 32 + i) * 16 + o] = sigm(acc);
        }

    } else {
        // =================== out0 ===================
        float* sMax0 = sm;               // [16*8]
        float* sMin0 = sm + 128;
        if (tid < 128) {
            int b = tid >> 3, c = tid & 7;
            const float* p = x1 + (b * 32) * 8 + c;
            float vmax = -INFINITY, vmin = INFINITY;
            #pragma unroll 8
            for (int n = 0; n < 32; n++) {
                float v = p[n * 8];
                vmax = fmaxf(vmax, v);
                vmin = fminf(vmin, v);
            }
            sMax0[tid] = vmax;
            sMin0[tid] = vmin;
        }
        __syncthreads();
        if (tid < 256) {
            int b = tid >> 4, o = tid & 15;
            float acc = b0[o];
            const float* x0b = x0 + b * 8;
            #pragma unroll
            for (int c = 0; c < 8; c++) {
                acc += x0b[c] * W0[c * 16 + o];
                acc += sMax0[b * 8 + c] * W0[(8 + c) * 16 + o];
                acc += sMin0[b * 8 + c] * W0[(16 + c) * 16 + o];
            }
            out0[b * 16 + o] = sigm(acc);
        }
    }
}

// ---------------------------------------------------------------------------
extern "C" void kernel_launch(void* const* d_in, const int* in_sizes, int n_in,
                              void* d_out, int out_size)
{
    const float* x0 = (const float*)d_in[0];
    const float* x1 = (const float*)d_in[1];
    const float* x2 = (const float*)d_in[2];
    const float* x3 = (const float*)d_in[3];
    const float* W0 = (const float*)d_in[4];
    const float* b0 = (const float*)d_in[5];
    const float* W1 = (const float*)d_in[6];
    const float* b1 = (const float*)d_in[7];
    const float* W2 = (const float*)d_in[8];
    const float* b2 = (const float*)d_in[9];
    const float* W3 = (const float*)d_in[10];
    const float* b3 = (const float*)d_in[11];

    float* out = (float*)d_out;
    float* out0 = out;                 // [16,16]            =     256
    float* out1 = out + 256;           // [16,32,16]         =    8192
    float* out2 = out + 8448;          // [16,32,32,16]      =  262144
    float* out3 = out + 270592;        // [16,32,32,32,16]   = 8388608

    const int smem_bytes = SM_FLOATS * 4;  // 231936
    cudaFuncSetAttribute(k_fused, cudaFuncAttributeMaxDynamicSharedMemorySize, smem_bytes);

    k_fused<<<530, 1024, smem_bytes>>>(x0, x1, x2, x3, W0, b0, W1, b1,
                                       W2, b2, W3, b3, out0, out1, out2, out3);
}